// round 13
// baseline (speedup 1.0000x reference)
#include <cuda_runtime.h>
#include <math.h>

#define GRID 128
#define NT   256
#define Bz   32
#define Sz   256
#define Iz   256
#define Hz   512
#define Nz   128
#define Cz   64
#define Oz   256
#define Pz   268
#define KV   832
#define KVP  836
#define WBP  516
#define MP   68
#define EPSF 1e-8f
#define SMEM_BYTES 219248

struct GState {
    unsigned flags[GRID];
    unsigned pad[32];
    float h[Bz * Hz];
    float r[Bz * Cz];
    float p[Bz * Pz];
    float outh[Bz * Oz];
};
__device__ GState gs;

extern __shared__ __align__(16) float sm[];

__device__ __forceinline__ float sg_(float x) { return 1.f / (1.f + expf(-x)); }
__device__ __forceinline__ float sp_(float x) { return (x > 20.f) ? x : log1pf(expf(x)); }

__device__ __forceinline__ unsigned long long ffma2_(unsigned long long a,
                                                     unsigned long long b,
                                                     unsigned long long c) {
    unsigned long long d;
    asm("fma.rn.f32x2 %0, %1, %2, %3;" : "=l"(d) : "l"(a), "l"(b), "l"(c));
    return d;
}
__device__ __forceinline__ float hsum2_(unsigned long long v) {
    float lo, hi;
    asm("mov.b64 {%0, %1}, %2;" : "=f"(lo), "=f"(hi) : "l"(v));
    return lo + hi;
}
// V row base: batch group of 8 gets +4 word skew (conflict-free octet loads)
__device__ __forceinline__ int voffb(int b) { return b * KVP + (b >> 3) * 4; }

// warp-0 polls 4 flags per lane with one LDG.128
__device__ __forceinline__ void poll4(unsigned target, int tid, int nlanes) {
    if (tid < nlanes) {
        const unsigned* fp = &gs.flags[tid * 4];
        for (;;) {
            unsigned a, b, c, d;
            asm volatile("ld.volatile.global.v4.u32 {%0,%1,%2,%3}, [%4];"
                         : "=r"(a), "=r"(b), "=r"(c), "=r"(d) : "l"(fp));
            if ((int)(a - target) >= 0 && (int)(b - target) >= 0 &&
                (int)(c - target) >= 0 && (int)(d - target) >= 0) break;
        }
    }
}

__device__ __forceinline__ void gbar_full(unsigned target, int tid, int bx) {
    __syncthreads();
    if (tid == 0) { __threadfence(); atomicExch(&gs.flags[bx], target); }
    poll4(target, tid, 32);
    __threadfence();
    __syncthreads();
}
// bar2: everyone arrives; only batch CTAs wait (on flags[0..63] = p producers)
__device__ __forceinline__ void gbar_p(unsigned target, int tid, int bx, bool isb) {
    __syncthreads();
    if (tid == 0) { __threadfence(); atomicExch(&gs.flags[bx], target); }
    if (isb) { poll4(target, tid, 16); __threadfence(); }
    __syncthreads();
}

__device__ __forceinline__ float grp_max128(float v, float* red, int tid) {
    #pragma unroll
    for (int o = 16; o > 0; o >>= 1) v = fmaxf(v, __shfl_xor_sync(0xffffffffu, v, o));
    int g4 = (tid >> 7) * 4;
    if ((tid & 31) == 0) red[g4 + ((tid >> 5) & 3)] = v;
    __syncthreads();
    float m = fmaxf(fmaxf(red[g4 + 0], red[g4 + 1]), fmaxf(red[g4 + 2], red[g4 + 3]));
    __syncthreads();
    return m;
}
__device__ __forceinline__ float grp_sum128(float v, float* red, int tid) {
    #pragma unroll
    for (int o = 16; o > 0; o >>= 1) v += __shfl_xor_sync(0xffffffffu, v, o);
    int g4 = (tid >> 7) * 4;
    if ((tid & 31) == 0) red[g4 + ((tid >> 5) & 3)] = v;
    __syncthreads();
    float m = (red[g4 + 0] + red[g4 + 1]) + (red[g4 + 2] + red[g4 + 3]);
    __syncthreads();
    return m;
}

// Gates GEMM pass: NKQ k-chunks x 4 batch-octets x RT rows = 256 threads.
// Each thread: 1 row x 8 batches x KLEN k. Warp-level V broadcast by design.
template<int NKQ, int RT, int KLEN>
__device__ __forceinline__ void gemmA2(const float* __restrict__ WAp,
                                       const float* __restrict__ V,
                                       float* __restrict__ gbuf,
                                       int tid, int k0, bool accum)
{
    const int kq   = tid / (4 * RT);
    const int rem  = tid - kq * (4 * RT);
    const int g    = rem / RT;
    const int rowg = rem - g * RT;
    const int kb   = k0 + kq * KLEN;
    const float* Vb = V + (g * 8) * KVP + g * 4 + kb;
    const float* Wp = WAp + rowg * KVP + kb;
    unsigned long long a[8];
    #pragma unroll
    for (int j = 0; j < 8; j++) a[j] = 0ull;
    #pragma unroll 4
    for (int k = 0; k < KLEN; k += 4) {
        ulonglong2 w = *(const ulonglong2*)(Wp + k);
        #pragma unroll
        for (int j = 0; j < 8; j++) {
            ulonglong2 v = *(const ulonglong2*)(Vb + j * KVP + k);
            a[j] = ffma2_(w.x, v.x, a[j]);
            a[j] = ffma2_(w.y, v.y, a[j]);
        }
    }
    float* gp = &gbuf[(kq * RT + rowg) * 33 + g * 8];
    #pragma unroll
    for (int j = 0; j < 8; j++) { float sv = hsum2_(a[j]); gp[j] = accum ? gp[j] + sv : sv; }
}

__global__ void __launch_bounds__(NT, 1)
ntm_kernel(const float* __restrict__ X,
           const float* __restrict__ Wih, const float* __restrict__ Whh,
           const float* __restrict__ bl,
           const float* __restrict__ Whd, const float* __restrict__ bhd,
           const float* __restrict__ Wout, const float* __restrict__ bout,
           float* __restrict__ Y)
{
    const int tid = threadIdx.x, bx = blockIdx.x;
    const bool isb = (bx < Bz);
    const int nunits = isb ? 1 : 5;
    const int nrows  = 4 * nunits;
    const int u_base = isb ? bx : (Bz + (bx - Bz) * 5);
    const int b0 = (bx & 1) * 16;   // B-phase batch half

    // ---- runtime smem layout (floats) ----
    float* WA   = sm;                        // nrows*KVP
    float* V    = WA + nrows * KVP;          // 32*KVP + 16
    float* WB   = V + (32 * KVP + 16);       // 9*WBP
    float* gb4a = WB + 9 * WBP;              // 4*16*33  (non-batch pass1)
    float* gb4b = gb4a + 2112;               // 16*4*33  (pass2 / batch)
    float* bA   = gb4b + 2112;               // 20
    float* bB   = bA + 20;                   // 12
    float* cst  = bB + 12;                   // 160
    float* red  = cst + 160;                 // 8
    float* scb  = red + 8;                   // 16
    float* tail = scb + 16;
    // batch tail
    float* M  = tail;                float* Mn = M + Nz * MP;
    float* wr = Mn + Nz;             float* ww = wr + Nz;
    float* t1 = ww + Nz;             float* pb = t1 + 256;
    float* kr = pb + Pz;             float* kw = kr + Cz;
    float* eb = kw + Cz;             float* ab = eb + Cz;
    // non-batch tail
    float* rbuf = tail;              // 64*32
    float* WoR  = rbuf + 2048;       // 3*64

    // ---------------- one-time staging ----------------
    for (int rr = 0; rr < nrows; rr++) {
        int q = rr / nunits, j = rr - q * nunits;
        int gr = q * Hz + u_base + j;
        for (int k = tid; k < KV; k += NT) {
            float v;
            if (k < 256)      v = Wih[gr * 320 + k];
            else if (k < 768) v = Whh[gr * Hz + (k - 256)];
            else              v = Wih[gr * 320 + 256 + (k - 768)];
            WA[rr * KVP + k] = v;
        }
    }
    if (tid < nrows) {
        int q = tid / nunits, j = tid - q * nunits;
        bA[tid] = bl[q * Hz + u_base + j];
    }
    const int baseB = (bx >> 1) * 9;
    const int cnt = (baseB >= 524) ? 0 : ((524 - baseB < 9) ? (524 - baseB) : 9);
    for (int rr = 0; rr < cnt; rr++) {
        int gr = baseB + rr;
        for (int k = tid; k < Hz; k += NT)
            WB[rr * WBP + k] = (gr < Pz) ? Whd[gr * Hz + k] : Wout[(gr - Pz) * 576 + k];
    }
    if (tid < cnt) {
        int gr = baseB + tid;
        bB[tid] = (gr < Pz) ? bhd[gr] : bout[gr - Pz];
    }
    if (!isb) {
        for (int i = tid; i < 3 * Cz; i += NT) {
            int o = (bx - Bz) * 3 + (i >> 6);
            if (o < Oz) WoR[i] = Wout[o * 576 + 512 + (i & 63)];
        }
    }
    for (int i = tid; i < 32 * KVP + 16; i += NT) V[i] = 0.f;
    for (int i = tid; i < 160; i += NT) cst[i] = 0.f;
    if (isb) {
        for (int i = tid; i < Nz * Cz; i += NT) M[(i >> 6) * MP + (i & 63)] = 0.01f;
        if (tid < Nz) {
            float w0 = (tid == 0) ? 1.f : 0.f;
            wr[tid] = w0; ww[tid] = w0; Mn[tid] = 0.08f;
        }
    }
    unsigned gen0 = *((volatile unsigned*)&gs.flags[bx]);
    unsigned nb = 0;
    __syncthreads();

    // ---------------- prologue: stage x(0), A-main(0) ----------------
    for (int i = tid; i < Bz * Iz / 4; i += NT) {
        int b = i >> 6, c4 = (i & 63) << 2;
        *(float4*)&V[voffb(b) + c4] =
            *(const float4*)&X[((size_t)b * Sz + 0) * Iz + c4];
    }
    __syncthreads();
    if (isb) {
        gemmA2<16, 4, 48>(WA, V, gb4b, tid, 0, false);
    } else {
        gemmA2<4, 16, 192>(WA, V, gb4a, tid, 0, false);
        gemmA2<16, 4, 48>(WA + 16 * KVP, V, gb4b, tid, 0, false);
    }
    __syncthreads();

    // ---------------- recurrence ----------------
    for (int t = 0; t < Sz; t++) {
        // == phase 1: stage x(t+1); stage r(t-1) ==
        if (t + 1 < Sz) {
            for (int i = tid; i < Bz * Iz / 4; i += NT) {
                int b = i >> 6, c4 = (i & 63) << 2;
                *(float4*)&V[voffb(b) + c4] =
                    *(const float4*)&X[((size_t)b * Sz + (t + 1)) * Iz + c4];
            }
        }
        if (t > 0) {
            for (int i = tid; i < Bz * Cz / 4; i += NT) {
                int b = i >> 4, c4 = (i & 15) << 2;
                *(float4*)&V[voffb(b) + 768 + c4] =
                    *(const float4*)&gs.r[b * Cz + c4];
            }
        }
        __syncthreads();
        // == phase 2: r-part of gates (accumulate; zeros at t=0) ==
        if (isb) {
            gemmA2<16, 4, 4>(WA, V, gb4b, tid, 768, true);
        } else {
            gemmA2<4, 16, 16>(WA, V, gb4a, tid, 768, true);
            gemmA2<16, 4, 4>(WA + 16 * KVP, V, gb4b, tid, 768, true);
        }
        __syncthreads();
        // == phase 3: LSTM; non-batch: D(t-1) ==
        if (tid < nunits * 32) {
            int j = tid >> 5, b = tid & 31;
            float G[4];
            #pragma unroll
            for (int g = 0; g < 4; g++) {
                int rr = g * nunits + j;
                float acc = bA[rr];
                if (isb) {
                    #pragma unroll
                    for (int kq = 0; kq < 16; kq++) acc += gb4b[(kq * 4 + rr) * 33 + b];
                } else if (rr < 16) {
                    #pragma unroll
                    for (int kq = 0; kq < 4; kq++) acc += gb4a[(kq * 16 + rr) * 33 + b];
                } else {
                    #pragma unroll
                    for (int kq = 0; kq < 16; kq++) acc += gb4b[(kq * 4 + rr - 16) * 33 + b];
                }
                G[g] = acc;
            }
            float c = sg_(G[1]) * cst[tid] + sg_(G[0]) * tanhf(G[2]);
            float h = sg_(G[3]) * tanhf(c);
            cst[tid] = c;
            gs.h[b * Hz + u_base + j] = h;
        }
        if (!isb && t > 0) {
            for (int i = tid; i < Bz * Cz / 4; i += NT) {
                int b = i >> 4, c4 = (i & 15) << 2;
                float4 rv = *(const float4*)&gs.r[b * Cz + c4];
                rbuf[(c4 + 0) * 32 + b] = rv.x;
                rbuf[(c4 + 1) * 32 + b] = rv.y;
                rbuf[(c4 + 2) * 32 + b] = rv.z;
                rbuf[(c4 + 3) * 32 + b] = rv.w;
            }
            __syncthreads();
            if (tid < 96) {
                int oi = tid >> 5, b = tid & 31, o = (bx - Bz) * 3 + oi;
                if (o < Oz) {
                    float a0 = 0.f, a1 = 0.f;
                    const float* wo = &WoR[oi * Cz];
                    #pragma unroll
                    for (int c = 0; c < 64; c += 2) {
                        a0 = fmaf(rbuf[c * 32 + b], wo[c], a0);
                        a1 = fmaf(rbuf[(c + 1) * 32 + b], wo[c + 1], a1);
                    }
                    Y[((size_t)b * Sz + (t - 1)) * Oz + o] = gs.outh[b * Oz + o] + a0 + a1;
                }
            }
        }
        gbar_full(gen0 + (++nb), tid, bx);   // bar1: h(t)

        // == phase 5: stage h (all 32 batches); B(t) ==
        for (int i = tid; i < Bz * Hz / 4; i += NT) {
            int b = i >> 7, c4 = (i & 127) << 2;
            *(float4*)&V[voffb(b) + 256 + c4] =
                *(const float4*)&gs.h[b * Hz + c4];
        }
        __syncthreads();
        if (tid < cnt * 16) {
            int rr = tid >> 4, b = tid & 15;
            const ulonglong2* Wp = (const ulonglong2*)&WB[rr * WBP];
            const ulonglong2* hp = (const ulonglong2*)&V[voffb(b0 + b) + 256];
            unsigned long long q0 = 0ull, q1 = 0ull, q2 = 0ull, q3 = 0ull;
            #pragma unroll 4
            for (int i = 0; i < 128; i += 2) {
                ulonglong2 w = Wp[i], v = hp[i];
                q0 = ffma2_(w.x, v.x, q0);
                q1 = ffma2_(w.y, v.y, q1);
                w = Wp[i + 1]; v = hp[i + 1];
                q2 = ffma2_(w.x, v.x, q2);
                q3 = ffma2_(w.y, v.y, q3);
            }
            float acc = (hsum2_(q0) + hsum2_(q1)) + (hsum2_(q2) + hsum2_(q3)) + bB[rr];
            int gr = baseB + rr;
            if (gr < Pz) gs.p[(b0 + b) * Pz + gr] = acc;
            else         gs.outh[(b0 + b) * Oz + (gr - Pz)] = acc;
        }
        gbar_p(gen0 + (++nb), tid, bx, isb); // bar2: p (batch waits only)

        // == phase 7: batch: C(t); all: A-main(t+1) ==
        if (isb) {
            for (int i = tid; i < Pz; i += NT) pb[i] = gs.p[bx * Pz + i];
            __syncthreads();
            if (tid < 64) {
                kr[tid] = pb[tid];
                kw[tid] = pb[70 + tid];
                eb[tid] = sg_(pb[140 + tid]);
                ab[tid] = pb[204 + tid];
            }
            if ((tid & 127) == 0) {
                int hh = tid >> 7, o = hh ? 70 : 0;
                float kn0 = 0.f, kn1 = 0.f;
                for (int c = 0; c < 64; c += 2) {
                    kn0 = fmaf(pb[o + c], pb[o + c], kn0);
                    kn1 = fmaf(pb[o + c + 1], pb[o + c + 1], kn1);
                }
                float kn = sqrtf(kn0 + kn1);
                float s0 = pb[o + 66], s1 = pb[o + 67], s2 = pb[o + 68];
                float mx = fmaxf(s0, fmaxf(s1, s2));
                float e0 = expf(s0 - mx), e1 = expf(s1 - mx), e2 = expf(s2 - mx);
                float inv = 1.f / (e0 + e1 + e2);
                float* c_ = &scb[hh * 8];
                c_[0] = sp_(pb[o + 64]);
                c_[1] = sg_(pb[o + 65]);
                c_[2] = e0 * inv; c_[3] = e1 * inv; c_[4] = e2 * inv;
                c_[5] = 1.f + sp_(pb[o + 69]);
                c_[6] = 1.f / (kn + EPSF);
            }
            __syncthreads();
            {
                const int hh = tid >> 7, n = tid & 127;
                const float* kk = hh ? kw : kr;
                float* wprev = hh ? ww : wr;
                const float* c_ = &scb[hh * 8];
                float* t1h = &t1[hh * Nz];
                float d0 = 0.f, d1 = 0.f, d2 = 0.f, d3 = 0.f;
                const float* Mp = &M[n * MP];
                #pragma unroll
                for (int c = 0; c < 64; c += 16) {
                    float4 m, k4;
                    m = *(const float4*)(Mp + c);      k4 = *(const float4*)(kk + c);
                    d0 = fmaf(m.x, k4.x, d0); d0 = fmaf(m.y, k4.y, d0);
                    d0 = fmaf(m.z, k4.z, d0); d0 = fmaf(m.w, k4.w, d0);
                    m = *(const float4*)(Mp + c + 4);  k4 = *(const float4*)(kk + c + 4);
                    d1 = fmaf(m.x, k4.x, d1); d1 = fmaf(m.y, k4.y, d1);
                    d1 = fmaf(m.z, k4.z, d1); d1 = fmaf(m.w, k4.w, d1);
                    m = *(const float4*)(Mp + c + 8);  k4 = *(const float4*)(kk + c + 8);
                    d2 = fmaf(m.x, k4.x, d2); d2 = fmaf(m.y, k4.y, d2);
                    d2 = fmaf(m.z, k4.z, d2); d2 = fmaf(m.w, k4.w, d2);
                    m = *(const float4*)(Mp + c + 12); k4 = *(const float4*)(kk + c + 12);
                    d3 = fmaf(m.x, k4.x, d3); d3 = fmaf(m.y, k4.y, d3);
                    d3 = fmaf(m.z, k4.z, d3); d3 = fmaf(m.w, k4.w, d3);
                }
                float d = (d0 + d1) + (d2 + d3);
                float val = c_[0] * d / (Mn[n] + EPSF) * c_[6];
                float mx = grp_max128(val, red, tid);
                float ex = expf(val - mx);
                float sum = grp_sum128(ex, red, tid);
                float wc = ex / sum;
                t1h[n] = c_[1] * wc + (1.f - c_[1]) * wprev[n];
                __syncthreads();
                float ws = c_[2] * t1h[(n + 1) & 127]
                         + c_[3] * t1h[n]
                         + c_[4] * t1h[(n + 127) & 127];
                float wp = powf(ws + EPSF, c_[5]);
                float sw = grp_sum128(wp, red, tid);
                wprev[n] = wp / sw;
            }
            __syncthreads();
            if (tid < 128) {
                float wwn = ww[tid];
                float* Mp = &M[tid * MP];
                float n0 = 0.f, n1 = 0.f;
                #pragma unroll
                for (int c = 0; c < 64; c += 2) {
                    float m0 = Mp[c] * (1.f - wwn * eb[c]) + wwn * ab[c];
                    float m1 = Mp[c + 1] * (1.f - wwn * eb[c + 1]) + wwn * ab[c + 1];
                    Mp[c] = m0; Mp[c + 1] = m1;
                    n0 = fmaf(m0, m0, n0); n1 = fmaf(m1, m1, n1);
                }
                Mn[tid] = sqrtf(n0 + n1);
            }
            __syncthreads();
            {
                int q = tid >> 6, c = tid & 63;
                float a0 = 0.f, a1 = 0.f;
                #pragma unroll
                for (int n2 = 0; n2 < 32; n2 += 2) {
                    a0 = fmaf(wr[q * 32 + n2], M[(q * 32 + n2) * MP + c], a0);
                    a1 = fmaf(wr[q * 32 + n2 + 1], M[(q * 32 + n2 + 1) * MP + c], a1);
                }
                t1[q * 64 + c] = a0 + a1;
            }
            __syncthreads();
            if (tid < 64)
                gs.r[bx * Cz + tid] = (t1[tid] + t1[64 + tid]) + (t1[128 + tid] + t1[192 + tid]);
            __syncthreads();
        }
        if (t + 1 < Sz) {
            if (isb) {
                gemmA2<16, 4, 48>(WA, V, gb4b, tid, 0, false);
            } else {
                gemmA2<4, 16, 192>(WA, V, gb4a, tid, 0, false);
                gemmA2<16, 4, 48>(WA + 16 * KVP, V, gb4b, tid, 0, false);
            }
        }
        gbar_full(gen0 + (++nb), tid, bx);   // bar3: r(t)
    }

    // ---------------- epilogue: D(255) ----------------
    if (!isb) {
        for (int i = tid; i < Bz * Cz / 4; i += NT) {
            int b = i >> 4, c4 = (i & 15) << 2;
            float4 rv = *(const float4*)&gs.r[b * Cz + c4];
            rbuf[(c4 + 0) * 32 + b] = rv.x;
            rbuf[(c4 + 1) * 32 + b] = rv.y;
            rbuf[(c4 + 2) * 32 + b] = rv.z;
            rbuf[(c4 + 3) * 32 + b] = rv.w;
        }
        __syncthreads();
        if (tid < 96) {
            int oi = tid >> 5, b = tid & 31, o = (bx - Bz) * 3 + oi;
            if (o < Oz) {
                float a0 = 0.f, a1 = 0.f;
                const float* wo = &WoR[oi * Cz];
                #pragma unroll
                for (int c = 0; c < 64; c += 2) {
                    a0 = fmaf(rbuf[c * 32 + b], wo[c], a0);
                    a1 = fmaf(rbuf[(c + 1) * 32 + b], wo[c + 1], a1);
                }
                Y[((size_t)b * Sz + (Sz - 1)) * Oz + o] = gs.outh[b * Oz + o] + a0 + a1;
            }
        }
    }
}

extern "C" void kernel_launch(void* const* d_in, const int* in_sizes, int n_in,
                              void* d_out, int out_size) {
    (void)in_sizes; (void)n_in; (void)out_size;
    const float* X    = (const float*)d_in[0];
    const float* Wih  = (const float*)d_in[1];
    const float* Whh  = (const float*)d_in[2];
    const float* bl   = (const float*)d_in[3];
    const float* Whd  = (const float*)d_in[4];
    const float* bhd  = (const float*)d_in[5];
    const float* Wout = (const float*)d_in[6];
    const float* bout = (const float*)d_in[7];
    float* Y = (float*)d_out;

    cudaFuncSetAttribute(ntm_kernel, cudaFuncAttributeMaxDynamicSharedMemorySize,
                         SMEM_BYTES);
    ntm_kernel<<<GRID, NT, SMEM_BYTES>>>(X, Wih, Whh, bl, Whd, bhd, Wout, bout, Y);
}